// round 9
// baseline (speedup 1.0000x reference)
#include <cuda_runtime.h>
#include <cuda_fp16.h>
#include <math.h>

#define NN 100000
#define NE 1600000
#define KT 25
#define XW_COLS 800   // KT*32
#define NB 782        // col>>7 buckets (99999>>7 = 781)

// ---------------- scratch (__device__ globals) ----------------
__device__ __half g_xw[(size_t)NN * XW_COLS];   // fp16 table, 160 MB
__device__ float g_xroot[NN * 32];
__device__ float g_rdot[NN];
__device__ float g_denom[NN];
__device__ int   g_cnt[1024];                   // bucket counters / offsets
__device__ uint4 g_rec[NE];                     // sorted edge records {row,col,p0,p1}

// ---------------- f32x2 helpers ----------------
__device__ __forceinline__ void ffma2(unsigned long long& acc, unsigned long long a,
                                      unsigned long long b) {
    asm("fma.rn.f32x2 %0, %1, %2, %0;" : "+l"(acc) : "l"(a), "l"(b));
}
__device__ __forceinline__ unsigned long long pack2(float x, float y) {
    unsigned long long r;
    asm("mov.b64 %0, {%1,%2};" : "=l"(r) : "f"(x), "f"(y));
    return r;
}
__device__ __forceinline__ float2 unpack2(unsigned long long v) {
    float2 r;
    asm("mov.b64 {%0,%1}, %2;" : "=f"(r.x), "=f"(r.y) : "l"(v));
    return r;
}

// ---------------- K_root: x_root = x@rw, rdot, init accumulators ----------------
__global__ void k_root(const float* __restrict__ x, const float* __restrict__ rw,
                       const float* __restrict__ att, float* __restrict__ out) {
    __shared__ float rws[1024];
    __shared__ float atts[32];
    int tid = threadIdx.x;
    if (blockIdx.x < 4) {                    // zero bucket counters for this launch
        int i = blockIdx.x * 256 + tid;
        if (i < 1024) g_cnt[i] = 0;
    }
    for (int i = tid; i < 1024; i += 256) rws[i] = rw[i];
    if (tid < 32) atts[tid] = att[tid];
    __syncthreads();
    int warp = tid >> 5, lane = tid & 31;
    int n = blockIdx.x * 8 + warp;          // 12500*8 = 100000 exact
    float xv = x[n * 32 + lane];
    float acc = 0.f;
#pragma unroll
    for (int f = 0; f < 32; f++) {
        float xf = __shfl_sync(0xffffffffu, xv, f);
        acc = fmaf(xf, rws[f * 32 + lane], acc);
    }
    g_xroot[n * 32 + lane] = acc;
    out[n * 32 + lane] = 0.f;               // zero edge accumulator
    float t = acc * atts[lane];
#pragma unroll
    for (int o = 16; o; o >>= 1) t += __shfl_xor_sync(0xffffffffu, t, o);
    if (lane == 0) { g_rdot[n] = t; g_denom[n] = 0.f; }
}

// ---------------- bucket sort: hist -> scan -> scatter ----------------
__global__ void k_hist(const int* __restrict__ ei) {
    int e = blockIdx.x * 256 + threadIdx.x;     // 6250*256 = NE exact
    atomicAdd(&g_cnt[ei[NE + e] >> 7], 1);
}

__global__ void k_scan() {                       // 1 block, 1024 threads
    __shared__ int s[1024];
    int t = threadIdx.x;
    int v = (t < NB) ? g_cnt[t] : 0;
    s[t] = v;
    __syncthreads();
#pragma unroll
    for (int o = 1; o < 1024; o <<= 1) {
        int u = (t >= o) ? s[t - o] : 0;
        __syncthreads();
        s[t] += u;
        __syncthreads();
    }
    if (t < NB) g_cnt[t] = s[t] - v;             // exclusive prefix = bucket base
}

__global__ void k_scatter(const int* __restrict__ ei, const float* __restrict__ ps) {
    int e = blockIdx.x * 256 + threadIdx.x;
    int row = ei[e], col = ei[NE + e];
    float2 p = reinterpret_cast<const float2*>(ps)[e];
    int pos = atomicAdd(&g_cnt[col >> 7], 1);
    uint4 r;
    r.x = (unsigned)row;
    r.y = (unsigned)col;
    r.z = __float_as_uint(p.x);
    r.w = __float_as_uint(p.y);
    g_rec[pos] = r;
}

// ---------------- K_xw: g_xw[n][k*32+o] = sum_f x[n][f]*W[k][f][o]  (fp16 out) ----
#define KB_STRIDE 1026
#define NKB 28
#define XS_STRIDE 33
#define WS_FLOATS (NKB * KB_STRIDE)    // 28728
#define K_XW_SMEM ((WS_FLOATS + 128 * XS_STRIDE) * 4)

__global__ void __launch_bounds__(256) k_xw(const float* __restrict__ x,
                                            const float* __restrict__ w) {
    extern __shared__ float sm[];
    float* Ws = sm;                    // [kb*1026 + f*32 + o]
    float* xs = sm + WS_FLOATS;        // [node_local*33 + f]
    int tid = threadIdx.x;
    int n0 = blockIdx.x * 128;

    for (int kb = 0; kb < NKB; kb++) {
        for (int i2 = tid; i2 < 513; i2 += 256) {
            float2 v = (kb < KT && i2 < 512) ? ((const float2*)w)[kb * 512 + i2]
                                             : make_float2(0.f, 0.f);
            *(float2*)&Ws[kb * KB_STRIDE + i2 * 2] = v;
        }
    }
    for (int i = tid; i < 128 * 32; i += 256) {
        int n = i >> 5, f = i & 31;
        int gn = n0 + n;
        xs[n * XS_STRIDE + f] = (gn < NN) ? x[gn * 32 + f] : 0.f;
    }
    __syncthreads();

    int tx = tid & 15, ty = tid >> 4;
    int coff = (tx * 8) & 31;

    for (int cc = 0; cc < 7; cc++) {
        int col0 = cc * 128 + tx * 8;
        int base = (col0 >> 5) * KB_STRIDE + coff;

        unsigned long long acc[8][4];
#pragma unroll
        for (int j = 0; j < 8; j++)
#pragma unroll
            for (int i = 0; i < 4; i++) acc[j][i] = 0ull;

#pragma unroll
        for (int f = 0; f < 32; f++) {
            unsigned long long wp[4];
#pragma unroll
            for (int i = 0; i < 4; i++) {
                float2 w2 = *(const float2*)&Ws[base + f * 32 + 2 * i];
                wp[i] = pack2(w2.x, w2.y);
            }
#pragma unroll
            for (int j = 0; j < 8; j++) {
                float xv = xs[(ty * 8 + j) * XS_STRIDE + f];
                unsigned long long xp = pack2(xv, xv);
#pragma unroll
                for (int i = 0; i < 4; i++) ffma2(acc[j][i], xp, wp[i]);
            }
        }

        if (col0 < XW_COLS) {
#pragma unroll
            for (int j = 0; j < 8; j++) {
                int n = n0 + ty * 8 + j;
                if (n < NN) {
                    uint4 v;
                    float2 p0 = unpack2(acc[j][0]);
                    float2 p1 = unpack2(acc[j][1]);
                    float2 p2 = unpack2(acc[j][2]);
                    float2 p3 = unpack2(acc[j][3]);
                    __half2 h0 = __floats2half2_rn(p0.x, p0.y);
                    __half2 h1 = __floats2half2_rn(p1.x, p1.y);
                    __half2 h2 = __floats2half2_rn(p2.x, p2.y);
                    __half2 h3 = __floats2half2_rn(p3.x, p3.y);
                    v.x = *(unsigned int*)&h0;
                    v.y = *(unsigned int*)&h1;
                    v.z = *(unsigned int*)&h2;
                    v.w = *(unsigned int*)&h3;
                    *(uint4*)(g_xw + (size_t)n * XW_COLS + col0) = v;
                }
            }
        }
    }
}

// ---------------- K_edge: one pass over col-sorted edge records ----------------
// 8 threads/edge; lane q owns outputs [4q, 4q+4)
__global__ void k_edge(const float* __restrict__ att, float* __restrict__ out) {
    int gid = blockIdx.x * 256 + threadIdx.x;   // 50000*256 = NE*8 exact
    int e = gid >> 3, q = gid & 7;
    uint4 r = __ldg(&g_rec[e]);                 // broadcast across the 8 lanes
    int row = (int)r.x;
    int col = (int)r.y;
    float p0 = __uint_as_float(r.z) * 4.f;
    float p1 = __uint_as_float(r.w) * 4.f;
    float fl0 = floorf(p0), fl1 = floorf(p1);
    float fr0 = p0 - fl0, fr1 = p1 - fl1;
    int i0 = (int)fl0, i1 = (int)fl1;
    i0 = max(0, min(3, i0));
    i1 = max(0, min(3, i1));
    float b0 = (1.f - fr0) * (1.f - fr1);
    float b1 = fr0 * (1.f - fr1);
    float b2 = (1.f - fr0) * fr1;
    float b3 = fr0 * fr1;
    int w0 = i0 + 5 * i1;   // corners: w0, w0+1, w0+5, w0+6

    const uint2* tb = (const uint2*)g_xw;       // uint2 = 4 halves
    size_t nb = (size_t)col * 200 + q;
    uint2 u0 = __ldg(tb + nb + (size_t)w0 * 8);
    uint2 u1 = __ldg(tb + nb + (size_t)(w0 + 1) * 8);
    uint2 u2 = __ldg(tb + nb + (size_t)(w0 + 5) * 8);
    uint2 u3 = __ldg(tb + nb + (size_t)(w0 + 6) * 8);

    float2 a0 = __half22float2(*(__half2*)&u0.x), a1 = __half22float2(*(__half2*)&u0.y);
    float2 c0 = __half22float2(*(__half2*)&u1.x), c1 = __half22float2(*(__half2*)&u1.y);
    float2 d0 = __half22float2(*(__half2*)&u2.x), d1 = __half22float2(*(__half2*)&u2.y);
    float2 e0 = __half22float2(*(__half2*)&u3.x), e1 = __half22float2(*(__half2*)&u3.y);

    float4 m;
    m.x = b0 * a0.x + b1 * c0.x + b2 * d0.x + b3 * e0.x;
    m.y = b0 * a0.y + b1 * c0.y + b2 * d0.y + b3 * e0.y;
    m.z = b0 * a1.x + b1 * c1.x + b2 * d1.x + b3 * e1.x;
    m.w = b0 * a1.y + b1 * c1.y + b2 * d1.y + b3 * e1.y;

    float4 av = __ldg(reinterpret_cast<const float4*>(att + 32) + q);
    float t = m.x * av.x + m.y * av.y + m.z * av.z + m.w * av.w;
    t += __shfl_xor_sync(0xffffffffu, t, 1);
    t += __shfl_xor_sync(0xffffffffu, t, 2);
    t += __shfl_xor_sync(0xffffffffu, t, 4);

    float alpha = g_rdot[row] + t;
    alpha = alpha > 0.f ? alpha : 0.2f * alpha;     // leaky relu
    float ex = __expf(alpha);                        // exact ratio, no max-shift
    if (q == 0) atomicAdd(&g_denom[row], ex);

    float* op = out + row * 32 + q * 4;
    asm volatile("red.global.add.v4.f32 [%0], {%1,%2,%3,%4};" ::
                 "l"(op), "f"(m.x * ex), "f"(m.y * ex), "f"(m.z * ex), "f"(m.w * ex)
                 : "memory");
}

// ---------------- K_fin ----------------
__global__ void k_fin(float* __restrict__ out, const float* __restrict__ bias) {
    int i = blockIdx.x * 256 + threadIdx.x;  // 12500*256 = 3.2M exact
    int n = i >> 5, o = i & 31;
    out[i] = out[i] / (g_denom[n] + 1e-16f) + g_xroot[i] + bias[o];
}

// ---------------- launch ----------------
extern "C" void kernel_launch(void* const* d_in, const int* in_sizes, int n_in,
                              void* d_out, int out_size) {
    const float* x    = (const float*)d_in[0];
    const int*   ei   = (const int*)  d_in[1];
    const float* ps   = (const float*)d_in[2];
    const float* w    = (const float*)d_in[3];
    const float* rw   = (const float*)d_in[4];
    const float* att  = (const float*)d_in[5];
    const float* bias = (const float*)d_in[6];
    float* out = (float*)d_out;

    cudaFuncSetAttribute(k_xw, cudaFuncAttributeMaxDynamicSharedMemorySize, K_XW_SMEM);

    k_root<<<NN / 8, 256>>>(x, rw, att, out);          // also zeros g_cnt
    k_hist<<<NE / 256, 256>>>(ei);
    k_scan<<<1, 1024>>>();
    k_scatter<<<NE / 256, 256>>>(ei, ps);
    k_xw<<<(NN + 127) / 128, 256, K_XW_SMEM>>>(x, w);
    k_edge<<<(NE * 8) / 256, 256>>>(att, out);
    k_fin<<<(NN * 32) / 256, 256>>>(out, bias);
}

// round 10
// speedup vs baseline: 1.1694x; 1.1694x over previous
#include <cuda_runtime.h>
#include <cuda_fp16.h>
#include <math.h>

#define NN 100000
#define NE 1600000
#define KT 25
#define XW_COLS 800   // KT*32

// ---------------- scratch (__device__ globals) ----------------
__device__ __half g_xw[(size_t)NN * XW_COLS];   // fp16 table, 160 MB
__device__ float g_xroot[NN * 32];
__device__ float g_rdot[NN];
__device__ int   g_cnt[NN];                     // per-row counters / scatter cursors
__device__ int   g_off[NN + 1];                 // row -> edge range in g_rec
__device__ uint4 g_rec[NE + 8];                 // row-sorted records {col,p0,p1,-}

// ---------------- f32x2 helpers ----------------
__device__ __forceinline__ void ffma2(unsigned long long& acc, unsigned long long a,
                                      unsigned long long b) {
    asm("fma.rn.f32x2 %0, %1, %2, %0;" : "+l"(acc) : "l"(a), "l"(b));
}
__device__ __forceinline__ unsigned long long pack2(float x, float y) {
    unsigned long long r;
    asm("mov.b64 %0, {%1,%2};" : "=l"(r) : "f"(x), "f"(y));
    return r;
}
__device__ __forceinline__ float2 unpack2(unsigned long long v) {
    float2 r;
    asm("mov.b64 {%0,%1}, %2;" : "=f"(r.x), "=f"(r.y) : "l"(v));
    return r;
}

// ---------------- K_root: x_root = x@rw, rdot; zero row counters ----------------
__global__ void k_root(const float* __restrict__ x, const float* __restrict__ rw,
                       const float* __restrict__ att) {
    __shared__ float rws[1024];
    __shared__ float atts[32];
    int tid = threadIdx.x;
    int gid = blockIdx.x * 256 + tid;
    if (gid < NN) g_cnt[gid] = 0;           // zero histogram counters
    for (int i = tid; i < 1024; i += 256) rws[i] = rw[i];
    if (tid < 32) atts[tid] = att[tid];
    __syncthreads();
    int warp = tid >> 5, lane = tid & 31;
    int n = blockIdx.x * 8 + warp;          // 12500*8 = 100000 exact
    float xv = x[n * 32 + lane];
    float acc = 0.f;
#pragma unroll
    for (int f = 0; f < 32; f++) {
        float xf = __shfl_sync(0xffffffffu, xv, f);
        acc = fmaf(xf, rws[f * 32 + lane], acc);
    }
    g_xroot[n * 32 + lane] = acc;
    float t = acc * atts[lane];
#pragma unroll
    for (int o = 16; o; o >>= 1) t += __shfl_xor_sync(0xffffffffu, t, o);
    if (lane == 0) g_rdot[n] = t;
}

// ---------------- row-bucket sort: hist -> scan -> scatter ----------------
__global__ void k_hist(const int* __restrict__ ei) {
    int e = blockIdx.x * 256 + threadIdx.x;     // 6250*256 = NE exact
    atomicAdd(&g_cnt[ei[e]], 1);                // return unused -> RED; 16/addr avg
}

#define CHUNK 98            // 1024*98 >= 100000
__global__ void k_scan() {                       // 1 block, 1024 threads
    __shared__ int s[1024];
    int t = threadIdx.x;
    int base = t * CHUNK;
    int sum = 0;
    for (int j = 0; j < CHUNK; j++) {
        int i = base + j;
        if (i < NN) sum += g_cnt[i];
    }
    s[t] = sum;
    __syncthreads();
#pragma unroll
    for (int o = 1; o < 1024; o <<= 1) {
        int u = (t >= o) ? s[t - o] : 0;
        __syncthreads();
        s[t] += u;
        __syncthreads();
    }
    int run = (t > 0) ? s[t - 1] : 0;            // exclusive block prefix
    for (int j = 0; j < CHUNK; j++) {
        int i = base + j;
        if (i < NN) {
            int c = g_cnt[i];
            g_off[i] = run;
            g_cnt[i] = run;                      // scatter cursor
            run += c;
        }
    }
    if (t == 0) g_off[NN] = NE;
}

__global__ void k_scatter(const int* __restrict__ ei, const float* __restrict__ ps) {
    int e = blockIdx.x * 256 + threadIdx.x;
    int row = ei[e], col = ei[NE + e];
    float2 p = reinterpret_cast<const float2*>(ps)[e];
    int pos = atomicAdd(&g_cnt[row], 1);         // ~16 ops/address: cheap
    uint4 r;
    r.x = (unsigned)col;
    r.y = __float_as_uint(p.x);
    r.z = __float_as_uint(p.y);
    r.w = 0u;
    g_rec[pos] = r;
}

// ---------------- K_xw: g_xw[n][k*32+o] = sum_f x[n][f]*W[k][f][o]  (fp16 out) ----
#define KB_STRIDE 1026
#define NKB 28
#define XS_STRIDE 33
#define WS_FLOATS (NKB * KB_STRIDE)    // 28728
#define K_XW_SMEM ((WS_FLOATS + 128 * XS_STRIDE) * 4)

__global__ void __launch_bounds__(256) k_xw(const float* __restrict__ x,
                                            const float* __restrict__ w) {
    extern __shared__ float sm[];
    float* Ws = sm;                    // [kb*1026 + f*32 + o]
    float* xs = sm + WS_FLOATS;        // [node_local*33 + f]
    int tid = threadIdx.x;
    int n0 = blockIdx.x * 128;

    for (int kb = 0; kb < NKB; kb++) {
        for (int i2 = tid; i2 < 513; i2 += 256) {
            float2 v = (kb < KT && i2 < 512) ? ((const float2*)w)[kb * 512 + i2]
                                             : make_float2(0.f, 0.f);
            *(float2*)&Ws[kb * KB_STRIDE + i2 * 2] = v;
        }
    }
    for (int i = tid; i < 128 * 32; i += 256) {
        int n = i >> 5, f = i & 31;
        int gn = n0 + n;
        xs[n * XS_STRIDE + f] = (gn < NN) ? x[gn * 32 + f] : 0.f;
    }
    __syncthreads();

    int tx = tid & 15, ty = tid >> 4;
    int coff = (tx * 8) & 31;

    for (int cc = 0; cc < 7; cc++) {
        int col0 = cc * 128 + tx * 8;
        int base = (col0 >> 5) * KB_STRIDE + coff;

        unsigned long long acc[8][4];
#pragma unroll
        for (int j = 0; j < 8; j++)
#pragma unroll
            for (int i = 0; i < 4; i++) acc[j][i] = 0ull;

#pragma unroll
        for (int f = 0; f < 32; f++) {
            unsigned long long wp[4];
#pragma unroll
            for (int i = 0; i < 4; i++) {
                float2 w2 = *(const float2*)&Ws[base + f * 32 + 2 * i];
                wp[i] = pack2(w2.x, w2.y);
            }
#pragma unroll
            for (int j = 0; j < 8; j++) {
                float xv = xs[(ty * 8 + j) * XS_STRIDE + f];
                unsigned long long xp = pack2(xv, xv);
#pragma unroll
                for (int i = 0; i < 4; i++) ffma2(acc[j][i], xp, wp[i]);
            }
        }

        if (col0 < XW_COLS) {
#pragma unroll
            for (int j = 0; j < 8; j++) {
                int n = n0 + ty * 8 + j;
                if (n < NN) {
                    uint4 v;
                    float2 p0 = unpack2(acc[j][0]);
                    float2 p1 = unpack2(acc[j][1]);
                    float2 p2 = unpack2(acc[j][2]);
                    float2 p3 = unpack2(acc[j][3]);
                    __half2 h0 = __floats2half2_rn(p0.x, p0.y);
                    __half2 h1 = __floats2half2_rn(p1.x, p1.y);
                    __half2 h2 = __floats2half2_rn(p2.x, p2.y);
                    __half2 h3 = __floats2half2_rn(p3.x, p3.y);
                    v.x = *(unsigned int*)&h0;
                    v.y = *(unsigned int*)&h1;
                    v.z = *(unsigned int*)&h2;
                    v.w = *(unsigned int*)&h3;
                    *(uint4*)(g_xw + (size_t)n * XW_COLS + col0) = v;
                }
            }
        }
    }
}

// ---------------- K_edge: row-sorted, register accumulation, NO atomics ------
// 256 thr = 8 warps per block; warp owns 2 rows; within warp: 4 edge-groups of
// 8 lanes; lane q of a group owns output features [4q,4q+4).
__global__ void __launch_bounds__(256) k_edge(const float* __restrict__ att,
                                              const float* __restrict__ bias,
                                              float* __restrict__ out) {
    int tid = threadIdx.x;
    int warp = tid >> 5, lane = tid & 31;
    int q = lane & 7, grp = lane >> 3;
    float4 av = __ldg(reinterpret_cast<const float4*>(att + 32) + q);

    for (int rr = 0; rr < 2; rr++) {
        int r = (blockIdx.x * 8 + warp) * 2 + rr;      // 6250*8*2 = 100000 exact
        int s = __ldg(&g_off[r]);
        int e = __ldg(&g_off[r + 1]);
        float rdot = __ldg(&g_rdot[r]);

        float4 acc = make_float4(0.f, 0.f, 0.f, 0.f);
        float dsum = 0.f;

        for (int base = s; base < e; base += 4) {
            int ei_idx = base + grp;
            bool valid = ei_idx < e;
            int idx = valid ? ei_idx : (e - 1);        // clamped, always in-bounds
            uint4 rec = __ldg(&g_rec[idx]);            // 64B/warp, broadcast in group
            int col = (int)rec.x;
            float p0 = __uint_as_float(rec.y) * 4.f;
            float p1 = __uint_as_float(rec.z) * 4.f;
            float fl0 = floorf(p0), fl1 = floorf(p1);
            float fr0 = p0 - fl0, fr1 = p1 - fl1;
            int i0 = max(0, min(3, (int)fl0));
            int i1 = max(0, min(3, (int)fl1));
            float b0 = (1.f - fr0) * (1.f - fr1);
            float b1 = fr0 * (1.f - fr1);
            float b2 = (1.f - fr0) * fr1;
            float b3 = fr0 * fr1;
            int w0 = i0 + 5 * i1;

            const uint2* tb = (const uint2*)g_xw;      // uint2 = 4 halves
            size_t nb = (size_t)col * 200 + q;
            uint2 u0 = __ldg(tb + nb + (size_t)w0 * 8);
            uint2 u1 = __ldg(tb + nb + (size_t)(w0 + 1) * 8);
            uint2 u2 = __ldg(tb + nb + (size_t)(w0 + 5) * 8);
            uint2 u3 = __ldg(tb + nb + (size_t)(w0 + 6) * 8);

            float2 a0 = __half22float2(*(__half2*)&u0.x), a1 = __half22float2(*(__half2*)&u0.y);
            float2 c0 = __half22float2(*(__half2*)&u1.x), c1 = __half22float2(*(__half2*)&u1.y);
            float2 d0 = __half22float2(*(__half2*)&u2.x), d1 = __half22float2(*(__half2*)&u2.y);
            float2 e0 = __half22float2(*(__half2*)&u3.x), e1 = __half22float2(*(__half2*)&u3.y);

            float4 m;
            m.x = b0 * a0.x + b1 * c0.x + b2 * d0.x + b3 * e0.x;
            m.y = b0 * a0.y + b1 * c0.y + b2 * d0.y + b3 * e0.y;
            m.z = b0 * a1.x + b1 * c1.x + b2 * d1.x + b3 * e1.x;
            m.w = b0 * a1.y + b1 * c1.y + b2 * d1.y + b3 * e1.y;

            float t = m.x * av.x + m.y * av.y + m.z * av.z + m.w * av.w;
            t += __shfl_xor_sync(0xffffffffu, t, 1);
            t += __shfl_xor_sync(0xffffffffu, t, 2);
            t += __shfl_xor_sync(0xffffffffu, t, 4);

            float alpha = rdot + t;
            alpha = alpha > 0.f ? alpha : 0.2f * alpha;   // leaky relu
            float ex = valid ? __expf(alpha) : 0.f;
            acc.x = fmaf(m.x, ex, acc.x);
            acc.y = fmaf(m.y, ex, acc.y);
            acc.z = fmaf(m.z, ex, acc.z);
            acc.w = fmaf(m.w, ex, acc.w);
            dsum += ex;
        }

        // combine the 4 edge-groups (xor 8, xor 16)
#pragma unroll
        for (int o = 8; o <= 16; o <<= 1) {
            acc.x += __shfl_xor_sync(0xffffffffu, acc.x, o);
            acc.y += __shfl_xor_sync(0xffffffffu, acc.y, o);
            acc.z += __shfl_xor_sync(0xffffffffu, acc.z, o);
            acc.w += __shfl_xor_sync(0xffffffffu, acc.w, o);
            dsum  += __shfl_xor_sync(0xffffffffu, dsum, o);
        }

        if (lane < 8) {
            float inv = 1.f / (dsum + 1e-16f);
            float4 xr = *reinterpret_cast<const float4*>(g_xroot + r * 32 + q * 4);
            float4 bi = __ldg(reinterpret_cast<const float4*>(bias) + q);
            float4 o4;
            o4.x = acc.x * inv + xr.x + bi.x;
            o4.y = acc.y * inv + xr.y + bi.y;
            o4.z = acc.z * inv + xr.z + bi.z;
            o4.w = acc.w * inv + xr.w + bi.w;
            *reinterpret_cast<float4*>(out + r * 32 + q * 4) = o4;
        }
    }
}

// ---------------- launch ----------------
extern "C" void kernel_launch(void* const* d_in, const int* in_sizes, int n_in,
                              void* d_out, int out_size) {
    const float* x    = (const float*)d_in[0];
    const int*   ei   = (const int*)  d_in[1];
    const float* ps   = (const float*)d_in[2];
    const float* w    = (const float*)d_in[3];
    const float* rw   = (const float*)d_in[4];
    const float* att  = (const float*)d_in[5];
    const float* bias = (const float*)d_in[6];
    float* out = (float*)d_out;

    cudaFuncSetAttribute(k_xw, cudaFuncAttributeMaxDynamicSharedMemorySize, K_XW_SMEM);

    k_root<<<NN / 8, 256>>>(x, rw, att);       // also zeros g_cnt
    k_hist<<<NE / 256, 256>>>(ei);
    k_scan<<<1, 1024>>>();
    k_scatter<<<NE / 256, 256>>>(ei, ps);
    k_xw<<<(NN + 127) / 128, 256, K_XW_SMEM>>>(x, w);
    k_edge<<<NN / 16, 256>>>(att, bias, out);
}

// round 11
// speedup vs baseline: 1.5053x; 1.2873x over previous
#include <cuda_runtime.h>
#include <cuda_fp16.h>
#include <math.h>

#define NN 100000
#define NE 1600000
#define KT 25
#define XW_COLS 800   // KT*32

// ---------------- scratch (__device__ globals) ----------------
__device__ __half g_xw[(size_t)NN * XW_COLS];   // fp16 table, 160 MB
__device__ float g_d[NN * KT];                  // d[n][k] = xw[n][k,:].att2  (10 MB, L2)
__device__ float g_xroot[NN * 32];
__device__ float g_rdot[NN];
__device__ float g_denom[NN];

// ---------------- f32x2 helpers ----------------
__device__ __forceinline__ void ffma2(unsigned long long& acc, unsigned long long a,
                                      unsigned long long b) {
    asm("fma.rn.f32x2 %0, %1, %2, %0;" : "+l"(acc) : "l"(a), "l"(b));
}
__device__ __forceinline__ unsigned long long pack2(float x, float y) {
    unsigned long long r;
    asm("mov.b64 %0, {%1,%2};" : "=l"(r) : "f"(x), "f"(y));
    return r;
}
__device__ __forceinline__ float2 unpack2(unsigned long long v) {
    float2 r;
    asm("mov.b64 {%0,%1}, %2;" : "=f"(r.x), "=f"(r.y) : "l"(v));
    return r;
}

// ---------------- K_root: x_root = x@rw, rdot, init accumulators ----------------
__global__ void k_root(const float* __restrict__ x, const float* __restrict__ rw,
                       const float* __restrict__ att, float* __restrict__ out) {
    __shared__ float rws[1024];
    __shared__ float atts[32];
    int tid = threadIdx.x;
    for (int i = tid; i < 1024; i += 256) rws[i] = rw[i];
    if (tid < 32) atts[tid] = att[tid];
    __syncthreads();
    int warp = tid >> 5, lane = tid & 31;
    int n = blockIdx.x * 8 + warp;          // 12500*8 = 100000 exact
    float xv = x[n * 32 + lane];
    float acc = 0.f;
#pragma unroll
    for (int f = 0; f < 32; f++) {
        float xf = __shfl_sync(0xffffffffu, xv, f);
        acc = fmaf(xf, rws[f * 32 + lane], acc);
    }
    g_xroot[n * 32 + lane] = acc;
    out[n * 32 + lane] = 0.f;               // zero edge accumulator
    float t = acc * atts[lane];
#pragma unroll
    for (int o = 16; o; o >>= 1) t += __shfl_xor_sync(0xffffffffu, t, o);
    if (lane == 0) { g_rdot[n] = t; g_denom[n] = 0.f; }
}

// ---------------- K_xw: g_xw[n][k*32+o] = sum_f x[n][f]*W[k][f][o]  (fp16 out)
//                  + epilogue: g_d[n][k] = sum_o xw[n][k*32+o]*att[32+o]
#define KB_STRIDE 1026
#define NKB 28
#define XS_STRIDE 33
#define WS_FLOATS (NKB * KB_STRIDE)    // 28728
#define K_XW_SMEM ((WS_FLOATS + 128 * XS_STRIDE) * 4)

__global__ void __launch_bounds__(256) k_xw(const float* __restrict__ x,
                                            const float* __restrict__ w,
                                            const float* __restrict__ att) {
    extern __shared__ float sm[];
    float* Ws = sm;                    // [kb*1026 + f*32 + o]
    float* xs = sm + WS_FLOATS;        // [node_local*33 + f]
    int tid = threadIdx.x;
    int n0 = blockIdx.x * 128;

    for (int kb = 0; kb < NKB; kb++) {
        for (int i2 = tid; i2 < 513; i2 += 256) {
            float2 v = (kb < KT && i2 < 512) ? ((const float2*)w)[kb * 512 + i2]
                                             : make_float2(0.f, 0.f);
            *(float2*)&Ws[kb * KB_STRIDE + i2 * 2] = v;
        }
    }
    for (int i = tid; i < 128 * 32; i += 256) {
        int n = i >> 5, f = i & 31;
        int gn = n0 + n;
        xs[n * XS_STRIDE + f] = (gn < NN) ? x[gn * 32 + f] : 0.f;
    }
    __syncthreads();

    int tx = tid & 15, ty = tid >> 4;
    int coff = (tx * 8) & 31;                    // output-feature offset 0/8/16/24

    float av[8];                                 // att2 slice for this thread's 8 cols
#pragma unroll
    for (int i = 0; i < 8; i++) av[i] = __ldg(&att[32 + coff + i]);

    for (int cc = 0; cc < 7; cc++) {
        int col0 = cc * 128 + tx * 8;
        int base = (col0 >> 5) * KB_STRIDE + coff;

        unsigned long long acc[8][4];
#pragma unroll
        for (int j = 0; j < 8; j++)
#pragma unroll
            for (int i = 0; i < 4; i++) acc[j][i] = 0ull;

#pragma unroll
        for (int f = 0; f < 32; f++) {
            unsigned long long wp[4];
#pragma unroll
            for (int i = 0; i < 4; i++) {
                float2 w2 = *(const float2*)&Ws[base + f * 32 + 2 * i];
                wp[i] = pack2(w2.x, w2.y);
            }
#pragma unroll
            for (int j = 0; j < 8; j++) {
                float xv = xs[(ty * 8 + j) * XS_STRIDE + f];
                unsigned long long xp = pack2(xv, xv);
#pragma unroll
                for (int i = 0; i < 4; i++) ffma2(acc[j][i], xp, wp[i]);
            }
        }

        bool colok = (col0 < XW_COLS);
#pragma unroll
        for (int j = 0; j < 8; j++) {
            int n = n0 + ty * 8 + j;
            float2 p0 = unpack2(acc[j][0]);
            float2 p1 = unpack2(acc[j][1]);
            float2 p2 = unpack2(acc[j][2]);
            float2 p3 = unpack2(acc[j][3]);

            // --- d epilogue: partial dot with att2, reduce over the 4-lane group
            float part = p0.x * av[0] + p0.y * av[1] + p1.x * av[2] + p1.y * av[3]
                       + p2.x * av[4] + p2.y * av[5] + p3.x * av[6] + p3.y * av[7];
            part += __shfl_xor_sync(0xffffffffu, part, 1);
            part += __shfl_xor_sync(0xffffffffu, part, 2);

            if (colok && n < NN) {
                if ((tx & 3) == 0) g_d[n * KT + (col0 >> 5)] = part;
                uint4 v;
                __half2 h0 = __floats2half2_rn(p0.x, p0.y);
                __half2 h1 = __floats2half2_rn(p1.x, p1.y);
                __half2 h2 = __floats2half2_rn(p2.x, p2.y);
                __half2 h3 = __floats2half2_rn(p3.x, p3.y);
                v.x = *(unsigned int*)&h0;
                v.y = *(unsigned int*)&h1;
                v.z = *(unsigned int*)&h2;
                v.w = *(unsigned int*)&h3;
                *(uint4*)(g_xw + (size_t)n * XW_COLS + col0) = v;
            }
        }
    }
}

// ---------------- K_edge: one pass, no shuffles, independent lanes ----------------
// 8 threads/edge; lane q owns outputs [4q, 4q+4)
__global__ void k_edge(const int* __restrict__ ei, const float* __restrict__ ps,
                       float* __restrict__ out) {
    int gid = blockIdx.x * 256 + threadIdx.x;   // 50000*256 = NE*8 exact
    int e = gid >> 3, q = gid & 7;
    int row = ei[e];
    int col = ei[NE + e];
    float2 p = *reinterpret_cast<const float2*>(ps + 2 * e);
    float p0 = p.x * 4.f, p1 = p.y * 4.f;
    float fl0 = floorf(p0), fl1 = floorf(p1);
    float fr0 = p0 - fl0, fr1 = p1 - fl1;
    int i0 = max(0, min(3, (int)fl0));
    int i1 = max(0, min(3, (int)fl1));
    float b0 = (1.f - fr0) * (1.f - fr1);
    float b1 = fr0 * (1.f - fr1);
    float b2 = (1.f - fr0) * fr1;
    float b3 = fr0 * fr1;
    int w0 = i0 + 5 * i1;   // corners: w0, w0+1, w0+5, w0+6

    // fp16 msg gathers: uint2 = 4 halves; index = col*200 + w*8 + q
    const uint2* tb = (const uint2*)g_xw;
    size_t nb = (size_t)col * 200 + q;
    uint2 u0 = __ldg(tb + nb + (size_t)w0 * 8);
    uint2 u1 = __ldg(tb + nb + (size_t)(w0 + 1) * 8);
    uint2 u2 = __ldg(tb + nb + (size_t)(w0 + 5) * 8);
    uint2 u3 = __ldg(tb + nb + (size_t)(w0 + 6) * 8);

    // alpha from the precomputed dot table (L2-resident, broadcast across 8 lanes)
    const float* dp = g_d + col * KT + w0;
    float alpha = __ldg(&g_rdot[row])
                + b0 * __ldg(dp) + b1 * __ldg(dp + 1)
                + b2 * __ldg(dp + 5) + b3 * __ldg(dp + 6);
    alpha = alpha > 0.f ? alpha : 0.2f * alpha;     // leaky relu
    float ex = __expf(alpha);                        // exact ratio, no max-shift
    if (q == 0) atomicAdd(&g_denom[row], ex);

    float2 a0 = __half22float2(*(__half2*)&u0.x), a1 = __half22float2(*(__half2*)&u0.y);
    float2 c0 = __half22float2(*(__half2*)&u1.x), c1 = __half22float2(*(__half2*)&u1.y);
    float2 d0 = __half22float2(*(__half2*)&u2.x), d1 = __half22float2(*(__half2*)&u2.y);
    float2 e0 = __half22float2(*(__half2*)&u3.x), e1 = __half22float2(*(__half2*)&u3.y);

    float4 m;
    m.x = b0 * a0.x + b1 * c0.x + b2 * d0.x + b3 * e0.x;
    m.y = b0 * a0.y + b1 * c0.y + b2 * d0.y + b3 * e0.y;
    m.z = b0 * a1.x + b1 * c1.x + b2 * d1.x + b3 * e1.x;
    m.w = b0 * a1.y + b1 * c1.y + b2 * d1.y + b3 * e1.y;

    float* op = out + row * 32 + q * 4;
    asm volatile("red.global.add.v4.f32 [%0], {%1,%2,%3,%4};" ::
                 "l"(op), "f"(m.x * ex), "f"(m.y * ex), "f"(m.z * ex), "f"(m.w * ex)
                 : "memory");
}

// ---------------- K_fin ----------------
__global__ void k_fin(float* __restrict__ out, const float* __restrict__ bias) {
    int i = blockIdx.x * 256 + threadIdx.x;  // 12500*256 = 3.2M exact
    int n = i >> 5, o = i & 31;
    out[i] = out[i] / (g_denom[n] + 1e-16f) + g_xroot[i] + bias[o];
}

// ---------------- launch ----------------
extern "C" void kernel_launch(void* const* d_in, const int* in_sizes, int n_in,
                              void* d_out, int out_size) {
    const float* x    = (const float*)d_in[0];
    const int*   ei   = (const int*)  d_in[1];
    const float* ps   = (const float*)d_in[2];
    const float* w    = (const float*)d_in[3];
    const float* rw   = (const float*)d_in[4];
    const float* att  = (const float*)d_in[5];
    const float* bias = (const float*)d_in[6];
    float* out = (float*)d_out;

    cudaFuncSetAttribute(k_xw, cudaFuncAttributeMaxDynamicSharedMemorySize, K_XW_SMEM);

    k_root<<<NN / 8, 256>>>(x, rw, att, out);
    k_xw<<<(NN + 127) / 128, 256, K_XW_SMEM>>>(x, w, att);
    k_edge<<<(NE * 8) / 256, 256>>>(ei, ps, out);
    k_fin<<<(NN * 32) / 256, 256>>>(out, bias);
}